// round 1
// baseline (speedup 1.0000x reference)
#include <cuda_runtime.h>

#define NROWS 16384
#define CDIM  128
#define FDIM  768
#define HDIM  768
#define NDOM  8
#define KCOLS 16

// ---------------- scratch (static device globals: no allocation) ----------------
__device__ int   g_cnt[NDOM];
__device__ int   g_off[NDOM + 1];
__device__ int   g_cur[NDOM];
__device__ int   g_perm[NROWS];
__device__ float g_conf[NROWS * 3];
__device__ float g_h[(size_t)NROWS * HDIM];   // relu(h), 48 MB

// ---------------- 0: zero counters ----------------
__global__ void k_zero() {
    if (threadIdx.x < NDOM) g_cnt[threadIdx.x] = 0;
}

// ---------------- 1: confidence features + per-domain counts ----------------
__global__ void k_conf(const float* __restrict__ z, const int* __restrict__ dom,
                       const int* __restrict__ cols) {
    int n = blockIdx.x * blockDim.x + threadIdx.x;
    if (n >= NROWS) return;
    int d = dom[n];
    float v[KCOLS];
#pragma unroll
    for (int i = 0; i < KCOLS; i++)
        v[i] = z[(size_t)n * CDIM + cols[d * KCOLS + i]];
    float m = v[0];
#pragma unroll
    for (int i = 1; i < KCOLS; i++) m = fmaxf(m, v[i]);
    float e[KCOLS];
    float s = 0.f;
#pragma unroll
    for (int i = 0; i < KCOLS; i++) { e[i] = expf(v[i] - m); s += e[i]; }
    float t1 = -1e30f, t2 = -1e30f;
#pragma unroll
    for (int i = 0; i < KCOLS; i++) {
        float x = v[i];
        if (x > t1) { t2 = t1; t1 = x; }
        else if (x > t2) { t2 = x; }
    }
    float inv = 1.f / s;
    float p1 = expf(t1 - m) * inv;
    float p2 = expf(t2 - m) * inv;
    float logZ = logf(s);
    float ent = 0.f;
#pragma unroll
    for (int i = 0; i < KCOLS; i++) {
        float pi = e[i] * inv;
        ent -= pi * (v[i] - m - logZ);
    }
    ent *= (1.f / logf((float)KCOLS));
    g_conf[n * 3 + 0] = p1;
    g_conf[n * 3 + 1] = p1 - p2;
    g_conf[n * 3 + 2] = ent;
    atomicAdd(&g_cnt[d], 1);
}

// ---------------- 2: tiny scan ----------------
__global__ void k_scan() {
    if (threadIdx.x == 0 && blockIdx.x == 0) {
        int acc = 0;
        for (int d = 0; d < NDOM; d++) {
            g_off[d] = acc;
            g_cur[d] = acc;
            acc += g_cnt[d];
        }
        g_off[NDOM] = acc;
    }
}

// ---------------- 3: scatter permutation ----------------
__global__ void k_scatter(const int* __restrict__ dom) {
    int n = blockIdx.x * blockDim.x + threadIdx.x;
    if (n >= NROWS) return;
    int d = dom[n];
    int pos = atomicAdd(&g_cur[d], 1);
    g_perm[pos] = n;
}

// ---------------- 4: copy z_base -> out ----------------
__global__ void k_copy(const float4* __restrict__ src, float4* __restrict__ dst) {
    int i = blockIdx.x * blockDim.x + threadIdx.x;
    if (i < NROWS * CDIM / 4) dst[i] = src[i];
}

// ---------------- 5: main GEMM  h = relu([feats|conf] @ W1[d] + b1[d]) ----------------
// 128x128 tile, K-chunks of 16, 8x8 per-thread micro-kernel, fp32.
#define TM 128
#define TN 128
#define TK 16

__global__ __launch_bounds__(256, 2) void k_gemm1(
    const float* __restrict__ feats, const float* __restrict__ W1,
    const float* __restrict__ b1) {
    int d = blockIdx.z;
    int seg0 = g_off[d], seg1 = g_off[d + 1];
    int row0 = seg0 + blockIdx.x * TM;
    if (row0 >= seg1) return;
    int colBase = blockIdx.y * TN;

    __shared__ float As[TK][TM];
    __shared__ float Bs[TK][TN];
    __shared__ int   sPerm[TM];

    int tid = threadIdx.x;
    if (tid < TM) {
        int r = row0 + tid;
        sPerm[tid] = (r < seg1) ? g_perm[r] : -1;
    }
    __syncthreads();

    const float* Wd = W1 + (size_t)d * (FDIM + 3) * HDIM;

    float acc[8][8];
#pragma unroll
    for (int i = 0; i < 8; i++)
#pragma unroll
        for (int j = 0; j < 8; j++) acc[i][j] = 0.f;

    int tx = tid & 15, ty = tid >> 4;

    for (int k0 = 0; k0 < FDIM; k0 += TK) {
        // load A (gathered rows), transposed into As[k][m]
#pragma unroll
        for (int li = 0; li < 2; li++) {
            int i = tid + li * 256;
            int m = i >> 2, kq = i & 3;
            int nrow = sPerm[m];
            float4 av = make_float4(0.f, 0.f, 0.f, 0.f);
            if (nrow >= 0)
                av = *(const float4*)(feats + (size_t)nrow * FDIM + k0 + kq * 4);
            As[kq * 4 + 0][m] = av.x;
            As[kq * 4 + 1][m] = av.y;
            As[kq * 4 + 2][m] = av.z;
            As[kq * 4 + 3][m] = av.w;
        }
        // load B
#pragma unroll
        for (int li = 0; li < 2; li++) {
            int i = tid + li * 256;
            int kk = i >> 5, jq = i & 31;
            *(float4*)&Bs[kk][jq * 4] =
                *(const float4*)(Wd + (size_t)(k0 + kk) * HDIM + colBase + jq * 4);
        }
        __syncthreads();
#pragma unroll
        for (int kk = 0; kk < TK; kk++) {
            float a[8], b[8];
            *(float4*)&a[0] = *(float4*)&As[kk][ty * 8];
            *(float4*)&a[4] = *(float4*)&As[kk][ty * 8 + 4];
            *(float4*)&b[0] = *(float4*)&Bs[kk][tx * 8];
            *(float4*)&b[4] = *(float4*)&Bs[kk][tx * 8 + 4];
#pragma unroll
            for (int i = 0; i < 8; i++)
#pragma unroll
                for (int j = 0; j < 8; j++) acc[i][j] += a[i] * b[j];
        }
        __syncthreads();
    }

    // epilogue: conf tail (3 rank-1) + bias + relu, write to g_h
    int colb = colBase + tx * 8;
    float t0[8], t1[8], t2[8], bb[8];
#pragma unroll
    for (int j = 0; j < 8; j++) {
        t0[j] = Wd[(size_t)(FDIM + 0) * HDIM + colb + j];
        t1[j] = Wd[(size_t)(FDIM + 1) * HDIM + colb + j];
        t2[j] = Wd[(size_t)(FDIM + 2) * HDIM + colb + j];
        bb[j] = b1[d * HDIM + colb + j];
    }
#pragma unroll
    for (int i = 0; i < 8; i++) {
        int n = sPerm[ty * 8 + i];
        if (n < 0) continue;
        float c0 = g_conf[n * 3 + 0];
        float c1 = g_conf[n * 3 + 1];
        float c2 = g_conf[n * 3 + 2];
        float o[8];
#pragma unroll
        for (int j = 0; j < 8; j++) {
            float vv = acc[i][j] + c0 * t0[j] + c1 * t1[j] + c2 * t2[j] + bb[j];
            o[j] = fmaxf(vv, 0.f);
        }
        float4* dst = (float4*)(g_h + (size_t)n * HDIM + colb);
        dst[0] = make_float4(o[0], o[1], o[2], o[3]);
        dst[1] = make_float4(o[4], o[5], o[6], o[7]);
    }
}

// ---------------- 6: second GEMM + scatter-add into out ----------------
// dz = relu_h @ W2[d] + b2;  out[n, cols[d]] += dz*alpha
// W2 half-staged in smem with 17-stride (conflict-free), 4 rows per warp,
// lanes own k-residues, butterfly-reduce the 16 partials.
#define KHALF 384

__global__ __launch_bounds__(256) void k_gemm2(
    const float* __restrict__ W2, const float* __restrict__ b2,
    const float* __restrict__ alphas, const int* __restrict__ cols,
    float* __restrict__ out) {
    __shared__ float Ws[KHALF * 17];

    int d = blockIdx.z;
    int seg0 = g_off[d], seg1 = g_off[d + 1];
    int rbase = seg0 + blockIdx.x * 256;
    if (rbase >= seg1) return;
    int rend = min(rbase + 256, seg1);

    int tid = threadIdx.x, warp = tid >> 5, lane = tid & 31;
    const float* W2d = W2 + (size_t)d * HDIM * KCOLS;
    float alpha = alphas[d];

    for (int hhalf = 0; hhalf < 2; hhalf++) {
        __syncthreads();
        for (int i = tid; i < KHALF * KCOLS; i += 256) {
            int kk = i >> 4, c = i & 15;
            Ws[kk * 17 + c] = W2d[(size_t)(hhalf * KHALF + kk) * KCOLS + c];
        }
        __syncthreads();

        for (int r0 = rbase + warp * 4; r0 < rend; r0 += 32) {
            int nr[4];
#pragma unroll
            for (int t = 0; t < 4; t++) {
                int r = r0 + t;
                nr[t] = (r < seg1) ? g_perm[r] : -1;
            }
            float acc[4][KCOLS];
#pragma unroll
            for (int t = 0; t < 4; t++)
#pragma unroll
                for (int c = 0; c < KCOLS; c++) acc[t][c] = 0.f;

            for (int it = 0; it < KHALF / 32; it++) {
                int kk = it * 32 + lane;
                float w[KCOLS];
#pragma unroll
                for (int c = 0; c < KCOLS; c++) w[c] = Ws[kk * 17 + c];
#pragma unroll
                for (int t = 0; t < 4; t++) {
                    float hv = 0.f;
                    if (nr[t] >= 0)
                        hv = g_h[(size_t)nr[t] * HDIM + hhalf * KHALF + kk];
#pragma unroll
                    for (int c = 0; c < KCOLS; c++) acc[t][c] += hv * w[c];
                }
            }
            // butterfly reduce across lanes
#pragma unroll
            for (int off = 16; off >= 1; off >>= 1) {
#pragma unroll
                for (int t = 0; t < 4; t++)
#pragma unroll
                    for (int c = 0; c < KCOLS; c++)
                        acc[t][c] += __shfl_xor_sync(0xffffffffu, acc[t][c], off);
            }
            if (lane < KCOLS) {
                int colIdx = cols[d * KCOLS + lane];
                float bterm = (hhalf == 0) ? b2[d * KCOLS + lane] * alpha : 0.f;
#pragma unroll
                for (int t = 0; t < 4; t++) {
                    if (nr[t] < 0) continue;
                    float v = 0.f;
#pragma unroll
                    for (int c = 0; c < KCOLS; c++)
                        if (lane == c) v = acc[t][c];
                    size_t oi = (size_t)nr[t] * CDIM + colIdx;
                    out[oi] = out[oi] + v * alpha + bterm;
                }
            }
        }
    }
}

// ---------------- launcher ----------------
extern "C" void kernel_launch(void* const* d_in, const int* in_sizes, int n_in,
                              void* d_out, int out_size) {
    const float* z      = (const float*)d_in[0];
    const int*   dom    = (const int*)d_in[1];
    const float* feats  = (const float*)d_in[2];
    const int*   cols   = (const int*)d_in[3];
    const float* W1     = (const float*)d_in[4];
    const float* b1     = (const float*)d_in[5];
    const float* W2     = (const float*)d_in[6];
    const float* b2     = (const float*)d_in[7];
    const float* alphas = (const float*)d_in[8];
    float* out = (float*)d_out;

    k_zero<<<1, 32>>>();
    k_conf<<<NROWS / 256, 256>>>(z, dom, cols);
    k_scan<<<1, 1>>>();
    k_scatter<<<NROWS / 256, 256>>>(dom);
    k_copy<<<(NROWS * CDIM / 4 + 255) / 256, 256>>>((const float4*)z, (float4*)out);

    dim3 g1(NROWS / TM, HDIM / TN, NDOM);   // over-provisioned row tiles; empty ones exit
    k_gemm1<<<g1, 256>>>(feats, W1, b1);

    dim3 g2((NROWS + 255) / 256, 1, NDOM);
    k_gemm2<<<g2, 256>>>(W2, b2, alphas, cols, out);
}

// round 3
// speedup vs baseline: 1.7339x; 1.7339x over previous
#include <cuda_runtime.h>
#include <cuda_bf16.h>
#include <cstdint>

#define NROWS 16384
#define CDIM  128
#define FDIM  768
#define HDIM  768
#define NDOM  8
#define KCOLS 16

// ---------------- gemm1 tiling ----------------
#define TM   128
#define TN   128
#define TKC  64                 // K elements per chunk
#define NCHUNK (FDIM / TKC)     // 12

// ---------------- scratch ----------------
__device__ int   g_cnt[NDOM];
__device__ int   g_off[NDOM + 1];
__device__ int   g_cur[NDOM];
__device__ int   g_perm[NROWS];
__device__ float g_conf[NROWS * 3];
__device__ float g_h[(size_t)NROWS * HDIM];                      // relu(h) fp32
__device__ __nv_bfloat16 g_fh[(size_t)NROWS * FDIM];             // feats hi
__device__ __nv_bfloat16 g_fl[(size_t)NROWS * FDIM];             // feats lo
__device__ __nv_bfloat16 g_w1t_h[(size_t)NDOM * HDIM * FDIM];    // W1^T hi: [d][n][k]
__device__ __nv_bfloat16 g_w1t_l[(size_t)NDOM * HDIM * FDIM];    // W1^T lo

// ---------------- helpers ----------------
__device__ __forceinline__ uint32_t smem_u32(const void* p) {
    uint32_t a;
    asm("{ .reg .u64 t; cvta.to.shared.u64 t, %1; cvt.u32.u64 %0, t; }" : "=r"(a) : "l"(p));
    return a;
}
#define SWZ128(bo) ((bo) ^ (((bo) >> 3) & 0x70))

__device__ __forceinline__ void cp16(uint32_t dst, const void* src, uint32_t sz) {
    asm volatile("cp.async.cg.shared.global [%0], [%1], 16, %2;"
                 :: "r"(dst), "l"(src), "r"(sz) : "memory");
}
#define CP_COMMIT() asm volatile("cp.async.commit_group;" ::: "memory")
#define CP_WAIT(n)  asm volatile("cp.async.wait_group %0;" :: "n"(n) : "memory")

__device__ __forceinline__ void ldx4(uint32_t r[4], uint32_t addr) {
    asm volatile("ldmatrix.sync.aligned.m8n8.x4.shared.b16 {%0,%1,%2,%3}, [%4];"
                 : "=r"(r[0]), "=r"(r[1]), "=r"(r[2]), "=r"(r[3]) : "r"(addr));
}
__device__ __forceinline__ void mma16816(float c[4], const uint32_t a[4], const uint32_t b[2]) {
    asm volatile("mma.sync.aligned.m16n8k16.row.col.f32.bf16.bf16.f32 "
                 "{%0,%1,%2,%3}, {%4,%5,%6,%7}, {%8,%9}, {%0,%1,%2,%3};"
                 : "+f"(c[0]), "+f"(c[1]), "+f"(c[2]), "+f"(c[3])
                 : "r"(a[0]), "r"(a[1]), "r"(a[2]), "r"(a[3]), "r"(b[0]), "r"(b[1]));
}

// ---------------- SMEM layout (dynamic) ----------------
#define S_PERM  0            // 128 ints
#define S_TILE  1024
#define S_STAGE 65536        // per-stage stride
#define S_AH    0
#define S_AL    16384
#define S_BH    32768
#define S_BL    49152
#define SMEM_SZ (1024 + 2 * 65536)

// ---------------- small kernels ----------------
__global__ void k_zero() { if (threadIdx.x < NDOM) g_cnt[threadIdx.x] = 0; }

__global__ void k_conf(const float* __restrict__ z, const int* __restrict__ dom,
                       const int* __restrict__ cols) {
    int n = blockIdx.x * blockDim.x + threadIdx.x;
    if (n >= NROWS) return;
    int d = dom[n];
    float v[KCOLS];
#pragma unroll
    for (int i = 0; i < KCOLS; i++) v[i] = z[(size_t)n * CDIM + cols[d * KCOLS + i]];
    float m = v[0];
#pragma unroll
    for (int i = 1; i < KCOLS; i++) m = fmaxf(m, v[i]);
    float e[KCOLS], s = 0.f;
#pragma unroll
    for (int i = 0; i < KCOLS; i++) { e[i] = expf(v[i] - m); s += e[i]; }
    float t1 = -1e30f, t2 = -1e30f;
#pragma unroll
    for (int i = 0; i < KCOLS; i++) {
        float x = v[i];
        if (x > t1) { t2 = t1; t1 = x; } else if (x > t2) { t2 = x; }
    }
    float inv = 1.f / s;
    float p1 = expf(t1 - m) * inv, p2 = expf(t2 - m) * inv;
    float logZ = logf(s), ent = 0.f;
#pragma unroll
    for (int i = 0; i < KCOLS; i++) { float pi = e[i] * inv; ent -= pi * (v[i] - m - logZ); }
    ent *= (1.f / logf((float)KCOLS));
    g_conf[n * 3 + 0] = p1;
    g_conf[n * 3 + 1] = p1 - p2;
    g_conf[n * 3 + 2] = ent;
    atomicAdd(&g_cnt[d], 1);
}

__global__ void k_scan() {
    if (threadIdx.x == 0 && blockIdx.x == 0) {
        int acc = 0;
        for (int d = 0; d < NDOM; d++) { g_off[d] = acc; g_cur[d] = acc; acc += g_cnt[d]; }
        g_off[NDOM] = acc;
    }
}

__global__ void k_scatter(const int* __restrict__ dom) {
    int n = blockIdx.x * blockDim.x + threadIdx.x;
    if (n >= NROWS) return;
    int pos = atomicAdd(&g_cur[dom[n]], 1);
    g_perm[pos] = n;
}

__global__ void k_copy(const float4* __restrict__ src, float4* __restrict__ dst) {
    int i = blockIdx.x * blockDim.x + threadIdx.x;
    if (i < NROWS * CDIM / 4) dst[i] = src[i];
}

// feats fp32 -> hi/lo bf16
__global__ void k_cvtf(const float* __restrict__ f) {
    int i = blockIdx.x * blockDim.x + threadIdx.x;   // one float4 each
    if (i >= NROWS * FDIM / 4) return;
    float4 v = ((const float4*)f)[i];
    float x[4] = {v.x, v.y, v.z, v.w};
    __nv_bfloat16 h[4], l[4];
#pragma unroll
    for (int t = 0; t < 4; t++) {
        h[t] = __float2bfloat16_rn(x[t]);
        l[t] = __float2bfloat16_rn(x[t] - __bfloat162float(h[t]));
    }
    __nv_bfloat162* dh = (__nv_bfloat162*)g_fh;
    __nv_bfloat162* dl = (__nv_bfloat162*)g_fl;
    dh[i * 2 + 0] = __nv_bfloat162(h[0], h[1]);
    dh[i * 2 + 1] = __nv_bfloat162(h[2], h[3]);
    dl[i * 2 + 0] = __nv_bfloat162(l[0], l[1]);
    dl[i * 2 + 1] = __nv_bfloat162(l[2], l[3]);
}

// W1[d][k][n] -> W1T hi/lo [d][n][k], smem-tiled transpose
__global__ void k_w1t(const float* __restrict__ W1) {
    __shared__ float t[32][33];
    int d = blockIdx.z;
    int k0 = blockIdx.x * 32, n0 = blockIdx.y * 32;
    int tx = threadIdx.x, ty = threadIdx.y;   // 32 x 8
    const float* src = W1 + (size_t)d * (FDIM + 3) * HDIM;
#pragma unroll
    for (int r = 0; r < 4; r++)
        t[ty + 8 * r][tx] = src[(size_t)(k0 + ty + 8 * r) * HDIM + n0 + tx];
    __syncthreads();
#pragma unroll
    for (int r = 0; r < 4; r++) {
        float v = t[tx][ty + 8 * r];
        size_t o = ((size_t)d * HDIM + n0 + ty + 8 * r) * FDIM + k0 + tx;
        __nv_bfloat16 h = __float2bfloat16_rn(v);
        g_w1t_h[o] = h;
        g_w1t_l[o] = __float2bfloat16_rn(v - __bfloat162float(h));
    }
}

// ---------------- gemm1: warp-MMA split-bf16 ----------------
__global__ __launch_bounds__(256, 1) void k_gemm1(const float* __restrict__ W1,
                                                  const float* __restrict__ b1) {
    int d = blockIdx.z;
    int seg0 = g_off[d], seg1 = g_off[d + 1];
    int row0 = seg0 + blockIdx.x * TM;
    if (row0 >= seg1) return;
    int colBase = blockIdx.y * TN;

    extern __shared__ char smem[];
    uint32_t sb = smem_u32(smem);
    int tid = threadIdx.x, wid = tid >> 5, lane = tid & 31;

    int* sPerm = (int*)(smem + S_PERM);
    if (tid < TM) {
        int r = row0 + tid;
        sPerm[tid] = (r < seg1) ? g_perm[r] : -1;
    }
    __syncthreads();

    const __nv_bfloat16* wh = g_w1t_h + ((size_t)d * HDIM + colBase) * FDIM;
    const __nv_bfloat16* wl = g_w1t_l + ((size_t)d * HDIM + colBase) * FDIM;

    // cached per-thread load indices for the copy loop
    int ldm = (tid & 1023) >> 3;        // used via rem below
    (void)ldm;

    // ---- pipeline: issue chunk into stage (c&1) ----
    // A: 2048 x 16B, B: 2048 x 16B -> 16 cp.async per thread
    auto issue = [&](int c) {
        int k0 = c * TKC;
        uint32_t stage = sb + S_TILE + (c & 1) * S_STAGE;
#pragma unroll
        for (int i = 0; i < 8; i++) {   // A
            int idx = i * 256 + tid;
            int half = idx >> 10, rem = idx & 1023;
            int m = rem >> 3, j = rem & 7;
            int n = sPerm[m];
            const __nv_bfloat16* base = half ? g_fl : g_fh;
            const __nv_bfloat16* src = base + ((n >= 0) ? ((size_t)n * FDIM + k0 + j * 8) : 0);
            uint32_t dst = stage + (half ? S_AL : S_AH) + SWZ128((uint32_t)(m * 128 + j * 16));
            cp16(dst, src, (n >= 0) ? 16u : 0u);
        }
#pragma unroll
        for (int i = 0; i < 8; i++) {   // B
            int idx = i * 256 + tid;
            int half = idx >> 10, rem = idx & 1023;
            int nn = rem >> 3, j = rem & 7;
            const __nv_bfloat16* src = (half ? wl : wh) + (size_t)nn * FDIM + k0 + j * 8;
            uint32_t dst = stage + (half ? S_BL : S_BH) + SWZ128((uint32_t)(nn * 128 + j * 16));
            cp16(dst, src, 16u);
        }
        CP_COMMIT();
    };

    int warp_m = wid & 1;      // 0..1  (rows warp_m*64 .. +64)
    int warp_n = wid >> 1;     // 0..3  (cols warp_n*32 .. +32)

    float acc[4][4][4];
#pragma unroll
    for (int a = 0; a < 4; a++)
#pragma unroll
        for (int b = 0; b < 4; b++)
#pragma unroll
            for (int q = 0; q < 4; q++) acc[a][b][q] = 0.f;

    // per-lane constant address pieces
    uint32_t xm = (uint32_t)((lane & 7) << 4);
    uint32_t laneA = (uint32_t)((warp_m * 64 + (lane & 15)) * 128);
    uint32_t colA = (uint32_t)((lane >> 4) * 16);
    uint32_t laneB = (uint32_t)((warp_n * 32 + ((lane >> 4) << 3) + (lane & 7)) * 128);
    uint32_t colB = (uint32_t)(((lane >> 3) & 1) * 16);

    issue(0);
    for (int c = 0; c < NCHUNK; c++) {
        if (c + 1 < NCHUNK) { issue(c + 1); CP_WAIT(1); }
        else                { CP_WAIT(0); }
        __syncthreads();

        uint32_t stage = sb + S_TILE + (c & 1) * S_STAGE;
        uint32_t AH = stage + S_AH, AL = stage + S_AL;
        uint32_t BH = stage + S_BH, BL = stage + S_BL;

#pragma unroll
        for (int kf = 0; kf < 4; kf++) {
            uint32_t kb = (uint32_t)(kf * 32);
            uint32_t Bh[4][2], Bl[4][2];
#pragma unroll
            for (int p = 0; p < 2; p++) {
                uint32_t off = laneB + (uint32_t)(p * 2048) + ((kb + colB) ^ xm);
                uint32_t q[4];
                ldx4(q, BH + off);
                Bh[2 * p][0] = q[0]; Bh[2 * p][1] = q[1];
                Bh[2 * p + 1][0] = q[2]; Bh[2 * p + 1][1] = q[3];
                ldx4(q, BL + off);
                Bl[2 * p][0] = q[0]; Bl[2 * p][1] = q[1];
                Bl[2 * p + 1][0] = q[2]; Bl[2 * p + 1][1] = q[3];
            }
            uint32_t Ah[4][4], Al[4][4];
#pragma unroll
            for (int mf = 0; mf < 4; mf++) {
                uint32_t off = laneA + (uint32_t)(mf * 2048) + ((kb + colA) ^ xm);
                ldx4(Ah[mf], AH + off);
                ldx4(Al[mf], AL + off);
            }
#pragma unroll
            for (int mf = 0; mf < 4; mf++)
#pragma unroll
                for (int nf = 0; nf < 4; nf++) {
                    mma16816(acc[mf][nf], Ah[mf], Bh[nf]);
                    mma16816(acc[mf][nf], Ah[mf], Bl[nf]);
                    mma16816(acc[mf][nf], Al[mf], Bh[nf]);
                }
        }
        __syncthreads();
    }

    // ---- epilogue: stage tails (3 conf rows + bias) into smem ----
    float* tails = (float*)(smem + S_TILE);   // [4][128]
    {
        const float* Wd = W1 + (size_t)d * (FDIM + 3) * HDIM;
#pragma unroll
        for (int i = 0; i < 2; i++) {
            int idx = i * 256 + tid;          // 0..511
            int r = idx >> 7, cc = idx & 127;
            tails[idx] = (r < 3) ? Wd[(size_t)(FDIM + r) * HDIM + colBase + cc]
                                 : b1[d * HDIM + colBase + cc];
        }
    }
    __syncthreads();

#pragma unroll
    for (int mf = 0; mf < 4; mf++) {
        int r0 = warp_m * 64 + mf * 16 + (lane >> 2);
        int na = sPerm[r0], nb = sPerm[r0 + 8];
        float a0 = 0.f, a1 = 0.f, a2 = 0.f, b0 = 0.f, b1v = 0.f, b2 = 0.f;
        if (na >= 0) { a0 = g_conf[na * 3]; a1 = g_conf[na * 3 + 1]; a2 = g_conf[na * 3 + 2]; }
        if (nb >= 0) { b0 = g_conf[nb * 3]; b1v = g_conf[nb * 3 + 1]; b2 = g_conf[nb * 3 + 2]; }
#pragma unroll
        for (int nf = 0; nf < 4; nf++) {
            int col = warp_n * 32 + nf * 8 + (lane & 3) * 2;
            float t0x = tails[col],       t0y = tails[col + 1];
            float t1x = tails[128 + col], t1y = tails[128 + col + 1];
            float t2x = tails[256 + col], t2y = tails[256 + col + 1];
            float tbx = tails[384 + col], tby = tails[384 + col + 1];
            if (na >= 0) {
                float vx = acc[mf][nf][0] + a0 * t0x + a1 * t1x + a2 * t2x + tbx;
                float vy = acc[mf][nf][1] + a0 * t0y + a1 * t1y + a2 * t2y + tby;
                *(float2*)(g_h + (size_t)na * HDIM + colBase + col) =
                    make_float2(fmaxf(vx, 0.f), fmaxf(vy, 0.f));
            }
            if (nb >= 0) {
                float vx = acc[mf][nf][2] + b0 * t0x + b1v * t1x + b2 * t2x + tbx;
                float vy = acc[mf][nf][3] + b0 * t0y + b1v * t1y + b2 * t2y + tby;
                *(float2*)(g_h + (size_t)nb * HDIM + colBase + col) =
                    make_float2(fmaxf(vx, 0.f), fmaxf(vy, 0.f));
            }
        }
    }
}

// ---------------- gemm2: dz = relu_h @ W2 + b2, scatter-add ----------------
#define KHALF 384

__global__ __launch_bounds__(256) void k_gemm2(
    const float* __restrict__ W2, const float* __restrict__ b2,
    const float* __restrict__ alphas, const int* __restrict__ cols,
    float* __restrict__ out) {
    __shared__ float Ws[KHALF * 17];

    int d = blockIdx.z;
    int seg0 = g_off[d], seg1 = g_off[d + 1];
    int rbase = seg0 + blockIdx.x * 256;
    if (rbase >= seg1) return;
    int rend = min(rbase + 256, seg1);

    int tid = threadIdx.x, warp = tid >> 5, lane = tid & 31;
    const float* W2d = W2 + (size_t)d * HDIM * KCOLS;
    float alpha = alphas[d];

    for (int hhalf = 0; hhalf < 2; hhalf++) {
        __syncthreads();
        for (int i = tid; i < KHALF * KCOLS; i += 256) {
            int kk = i >> 4, c = i & 15;
            Ws[kk * 17 + c] = W2d[(size_t)(hhalf * KHALF + kk) * KCOLS + c];
        }
        __syncthreads();

        for (int r0 = rbase + warp * 4; r0 < rend; r0 += 32) {
            int nr[4];
#pragma unroll
            for (int t = 0; t < 4; t++) {
                int r = r0 + t;
                nr[t] = (r < seg1) ? g_perm[r] : -1;
            }
            float acc[4][KCOLS];
#pragma unroll
            for (int t = 0; t < 4; t++)
#pragma unroll
                for (int c = 0; c < KCOLS; c++) acc[t][c] = 0.f;

            for (int it = 0; it < KHALF / 32; it++) {
                int kk = it * 32 + lane;
                float w[KCOLS];
#pragma unroll
                for (int c = 0; c < KCOLS; c++) w[c] = Ws[kk * 17 + c];
#pragma unroll
                for (int t = 0; t < 4; t++) {
                    float hv = 0.f;
                    if (nr[t] >= 0)
                        hv = g_h[(size_t)nr[t] * HDIM + hhalf * KHALF + kk];
#pragma unroll
                    for (int c = 0; c < KCOLS; c++) acc[t][c] += hv * w[c];
                }
            }
#pragma unroll
            for (int off = 16; off >= 1; off >>= 1) {
#pragma unroll
                for (int t = 0; t < 4; t++)
#pragma unroll
                    for (int c = 0; c < KCOLS; c++)
                        acc[t][c] += __shfl_xor_sync(0xffffffffu, acc[t][c], off);
            }
            if (lane < KCOLS) {
                int colIdx = cols[d * KCOLS + lane];
                float bterm = (hhalf == 0) ? b2[d * KCOLS + lane] * alpha : 0.f;
#pragma unroll
                for (int t = 0; t < 4; t++) {
                    if (nr[t] < 0) continue;
                    float v = 0.f;
#pragma unroll
                    for (int c = 0; c < KCOLS; c++)
                        if (lane == c) v = acc[t][c];
                    size_t oi = (size_t)nr[t] * CDIM + colIdx;
                    out[oi] = out[oi] + v * alpha + bterm;
                }
            }
        }
    }
}

// ---------------- launcher ----------------
extern "C" void kernel_launch(void* const* d_in, const int* in_sizes, int n_in,
                              void* d_out, int out_size) {
    const float* z      = (const float*)d_in[0];
    const int*   dom    = (const int*)d_in[1];
    const float* feats  = (const float*)d_in[2];
    const int*   cols   = (const int*)d_in[3];
    const float* W1     = (const float*)d_in[4];
    const float* b1     = (const float*)d_in[5];
    const float* W2     = (const float*)d_in[6];
    const float* b2     = (const float*)d_in[7];
    const float* alphas = (const float*)d_in[8];
    float* out = (float*)d_out;

    cudaFuncSetAttribute(k_gemm1, cudaFuncAttributeMaxDynamicSharedMemorySize, SMEM_SZ);

    k_zero<<<1, 32>>>();
    k_conf<<<NROWS / 256, 256>>>(z, dom, cols);
    k_scan<<<1, 1>>>();
    k_scatter<<<NROWS / 256, 256>>>(dom);
    k_copy<<<NROWS * CDIM / 4 / 256, 256>>>((const float4*)z, (float4*)out);
    k_cvtf<<<NROWS * FDIM / 4 / 256, 256>>>(feats);
    dim3 gw(FDIM / 32, HDIM / 32, NDOM);
    k_w1t<<<gw, dim3(32, 8)>>>(W1);

    dim3 g1(32, HDIM / TN, NDOM);   // over-provisioned row tiles; empty ones exit
    k_gemm1<<<g1, 256, SMEM_SZ>>>(W1, b1);

    dim3 g2((NROWS + 255) / 256, 1, NDOM);
    k_gemm2<<<g2, 256>>>(W2, b2, alphas, cols, out);
}

// round 5
// speedup vs baseline: 4.0882x; 2.3578x over previous
#include <cuda_runtime.h>
#include <cuda_fp16.h>
#include <cstdint>

#define NROWS 16384
#define CDIM  128
#define FDIM  768
#define HDIM  768
#define NDOM  8
#define KCOLS 16

#define TM   128
#define TN   128
#define TKC  64
#define NCHUNK (FDIM / TKC)     // 12
#define NSLICE (HDIM / TN)      // 6

// ---------------- scratch ----------------
__device__ int    g_cnt[NDOM];
__device__ int    g_off[NDOM + 1];
__device__ int    g_cur[NDOM];
__device__ int    g_perm[NROWS];
__device__ float  g_conf[NROWS * 3];
__device__ __half g_f[(size_t)NROWS * FDIM];                   // feats fp16
__device__ __half g_w1t[(size_t)NDOM * HDIM * FDIM];           // W1^T fp16 [d][n][k]
__device__ float  g_dz[(size_t)NSLICE * NROWS * KCOLS];        // partial dz per col-slice

// ---------------- helpers ----------------
__device__ __forceinline__ uint32_t smem_u32(const void* p) {
    uint32_t a;
    asm("{ .reg .u64 t; cvta.to.shared.u64 t, %1; cvt.u32.u64 %0, t; }" : "=r"(a) : "l"(p));
    return a;
}
#define SWZ128(bo) ((bo) ^ (((bo) >> 3) & 0x70))

__device__ __forceinline__ void cp16(uint32_t dst, const void* src, uint32_t sz) {
    asm volatile("cp.async.cg.shared.global [%0], [%1], 16, %2;"
                 :: "r"(dst), "l"(src), "r"(sz) : "memory");
}
#define CP_COMMIT() asm volatile("cp.async.commit_group;" ::: "memory")
#define CP_WAIT(n)  asm volatile("cp.async.wait_group %0;" :: "n"(n) : "memory")

__device__ __forceinline__ void ldx4(uint32_t r[4], uint32_t addr) {
    asm volatile("ldmatrix.sync.aligned.m8n8.x4.shared.b16 {%0,%1,%2,%3}, [%4];"
                 : "=r"(r[0]), "=r"(r[1]), "=r"(r[2]), "=r"(r[3]) : "r"(addr));
}
__device__ __forceinline__ void mma16816(float c[4], const uint32_t a[4], const uint32_t b[2]) {
    asm volatile("mma.sync.aligned.m16n8k16.row.col.f32.f16.f16.f32 "
                 "{%0,%1,%2,%3}, {%4,%5,%6,%7}, {%8,%9}, {%0,%1,%2,%3};"
                 : "+f"(c[0]), "+f"(c[1]), "+f"(c[2]), "+f"(c[3])
                 : "r"(a[0]), "r"(a[1]), "r"(a[2]), "r"(a[3]), "r"(b[0]), "r"(b[1]));
}

// ---------------- SMEM layout ----------------
#define S_PERM  0            // 128 ints
#define S_TILE  1024
#define S_STAGE 32768        // A 16KB + B 16KB
#define S_A     0
#define S_B     16384
// epilogue (reuses tile area):
//   tails  4*128 f32  @ S_TILE          (2048 B)
//   W2s    128*17 f32 @ S_TILE + 2048   (8704 B)
//   dzbuf  4*128*16 f32 @ S_TILE + 12288 (32768 B)
#define S_DZB   (S_TILE + 12288)
#define SMEM_SZ (1024 + 2 * 32768)

// ---------------- small kernels ----------------
__global__ void k_zero() { if (threadIdx.x < NDOM) g_cnt[threadIdx.x] = 0; }

__global__ void k_conf(const float* __restrict__ z, const int* __restrict__ dom,
                       const int* __restrict__ cols) {
    int n = blockIdx.x * blockDim.x + threadIdx.x;
    if (n >= NROWS) return;
    int d = dom[n];
    float v[KCOLS];
#pragma unroll
    for (int i = 0; i < KCOLS; i++) v[i] = z[(size_t)n * CDIM + cols[d * KCOLS + i]];
    float m = v[0];
#pragma unroll
    for (int i = 1; i < KCOLS; i++) m = fmaxf(m, v[i]);
    float e[KCOLS], s = 0.f;
#pragma unroll
    for (int i = 0; i < KCOLS; i++) { e[i] = expf(v[i] - m); s += e[i]; }
    float t1 = -1e30f, t2 = -1e30f;
#pragma unroll
    for (int i = 0; i < KCOLS; i++) {
        float x = v[i];
        if (x > t1) { t2 = t1; t1 = x; } else if (x > t2) { t2 = x; }
    }
    float inv = 1.f / s;
    float p1 = expf(t1 - m) * inv, p2 = expf(t2 - m) * inv;
    float logZ = logf(s), ent = 0.f;
#pragma unroll
    for (int i = 0; i < KCOLS; i++) { float pi = e[i] * inv; ent -= pi * (v[i] - m - logZ); }
    ent *= (1.f / logf((float)KCOLS));
    g_conf[n * 3 + 0] = p1;
    g_conf[n * 3 + 1] = p1 - p2;
    g_conf[n * 3 + 2] = ent;
    atomicAdd(&g_cnt[d], 1);
}

__global__ void k_scan() {
    if (threadIdx.x == 0 && blockIdx.x == 0) {
        int acc = 0;
        for (int d = 0; d < NDOM; d++) { g_off[d] = acc; g_cur[d] = acc; acc += g_cnt[d]; }
        g_off[NDOM] = acc;
    }
}

__global__ void k_scatter(const int* __restrict__ dom) {
    int n = blockIdx.x * blockDim.x + threadIdx.x;
    if (n >= NROWS) return;
    int pos = atomicAdd(&g_cur[dom[n]], 1);
    g_perm[pos] = n;
}

// feats fp32 -> fp16
__global__ void k_cvtf(const float* __restrict__ f) {
    int i = blockIdx.x * blockDim.x + threadIdx.x;   // one float4 each
    if (i >= NROWS * FDIM / 4) return;
    float4 v = ((const float4*)f)[i];
    __half2* dst = (__half2*)g_f;
    dst[i * 2 + 0] = __floats2half2_rn(v.x, v.y);
    dst[i * 2 + 1] = __floats2half2_rn(v.z, v.w);
}

// W1[d][k][n] -> W1T fp16 [d][n][k]
__global__ void k_w1t(const float* __restrict__ W1) {
    __shared__ float t[32][33];
    int d = blockIdx.z;
    int k0 = blockIdx.x * 32, n0 = blockIdx.y * 32;
    int tx = threadIdx.x, ty = threadIdx.y;   // 32 x 8
    const float* src = W1 + (size_t)d * (FDIM + 3) * HDIM;
#pragma unroll
    for (int r = 0; r < 4; r++)
        t[ty + 8 * r][tx] = src[(size_t)(k0 + ty + 8 * r) * HDIM + n0 + tx];
    __syncthreads();
#pragma unroll
    for (int r = 0; r < 4; r++) {
        size_t o = ((size_t)d * HDIM + n0 + ty + 8 * r) * FDIM + k0 + tx;
        g_w1t[o] = __float2half_rn(t[tx][ty + 8 * r]);
    }
}

// ---------------- fused gemm1 + gemm2-partial ----------------
__global__ __launch_bounds__(256, 2) void k_gemm1(
    const float* __restrict__ W1, const float* __restrict__ b1,
    const float* __restrict__ W2, const float* __restrict__ alphas,
    const int* __restrict__ cols) {
    int d = blockIdx.z;
    int seg0 = g_off[d], seg1 = g_off[d + 1];
    int row0 = seg0 + blockIdx.x * TM;
    if (row0 >= seg1) return;
    int slice = blockIdx.y;
    int colBase = slice * TN;

    extern __shared__ char smem[];
    uint32_t sb = smem_u32(smem);
    int tid = threadIdx.x, wid = tid >> 5, lane = tid & 31;

    int* sPerm = (int*)(smem + S_PERM);
    if (tid < TM) {
        int r = row0 + tid;
        sPerm[tid] = (r < seg1) ? g_perm[r] : -1;
    }
    __syncthreads();

    const __half* wptr = g_w1t + ((size_t)d * HDIM + colBase) * FDIM;

    auto issue = [&](int c) {
        int k0 = c * TKC;
        uint32_t stage = sb + S_TILE + (c & 1) * S_STAGE;
#pragma unroll
        for (int i = 0; i < 4; i++) {   // A: 1024 x 16B
            int idx = i * 256 + tid;
            int m = idx >> 3, j = idx & 7;
            int n = sPerm[m];
            const __half* src = g_f + ((n >= 0) ? ((size_t)n * FDIM + k0 + j * 8) : 0);
            uint32_t dst = stage + S_A + SWZ128((uint32_t)(m * 128 + j * 16));
            cp16(dst, src, (n >= 0) ? 16u : 0u);
        }
#pragma unroll
        for (int i = 0; i < 4; i++) {   // B: 1024 x 16B
            int idx = i * 256 + tid;
            int nn = idx >> 3, j = idx & 7;
            const __half* src = wptr + (size_t)nn * FDIM + k0 + j * 8;
            uint32_t dst = stage + S_B + SWZ128((uint32_t)(nn * 128 + j * 16));
            cp16(dst, src, 16u);
        }
        CP_COMMIT();
    };

    int warp_m = wid & 1;      // rows warp_m*64 .. +64
    int warp_n = wid >> 1;     // cols warp_n*32 .. +32

    float acc[4][4][4];
#pragma unroll
    for (int a = 0; a < 4; a++)
#pragma unroll
        for (int b = 0; b < 4; b++)
#pragma unroll
            for (int q = 0; q < 4; q++) acc[a][b][q] = 0.f;

    uint32_t xm = (uint32_t)((lane & 7) << 4);
    uint32_t laneA = (uint32_t)((warp_m * 64 + (lane & 15)) * 128);
    uint32_t colA = (uint32_t)((lane >> 4) * 16);
    uint32_t laneB = (uint32_t)((warp_n * 32 + ((lane >> 4) << 3) + (lane & 7)) * 128);
    uint32_t colB = (uint32_t)(((lane >> 3) & 1) * 16);

    issue(0);
    for (int c = 0; c < NCHUNK; c++) {
        if (c + 1 < NCHUNK) { issue(c + 1); CP_WAIT(1); }
        else                { CP_WAIT(0); }
        __syncthreads();

        uint32_t stage = sb + S_TILE + (c & 1) * S_STAGE;
        uint32_t A = stage + S_A, B = stage + S_B;

#pragma unroll
        for (int kf = 0; kf < 4; kf++) {
            uint32_t kb = (uint32_t)(kf * 32);
            uint32_t Bh[4][2];
#pragma unroll
            for (int p = 0; p < 2; p++) {
                uint32_t off = laneB + (uint32_t)(p * 2048) + ((kb + colB) ^ xm);
                uint32_t q[4];
                ldx4(q, B + off);
                Bh[2 * p][0] = q[0]; Bh[2 * p][1] = q[1];
                Bh[2 * p + 1][0] = q[2]; Bh[2 * p + 1][1] = q[3];
            }
            uint32_t Ah[4][4];
#pragma unroll
            for (int mf = 0; mf < 4; mf++) {
                uint32_t off = laneA + (uint32_t)(mf * 2048) + ((kb + colA) ^ xm);
                ldx4(Ah[mf], A + off);
            }
#pragma unroll
            for (int mf = 0; mf < 4; mf++)
#pragma unroll
                for (int nf = 0; nf < 4; nf++)
                    mma16816(acc[mf][nf], Ah[mf], Bh[nf]);
        }
        __syncthreads();
    }

    // ---- stage epilogue tables ----
    float* tails = (float*)(smem + S_TILE);            // [4][128]
    float* W2s   = (float*)(smem + S_TILE + 2048);     // [128][17] alpha-prescaled
    float* dzbuf = (float*)(smem + S_DZB);             // [4 warp_n][128][16]
    {
        const float* Wd = W1 + (size_t)d * (FDIM + 3) * HDIM;
#pragma unroll
        for (int i = 0; i < 2; i++) {
            int idx = i * 256 + tid;
            int r = idx >> 7, cc = idx & 127;
            tails[idx] = (r < 3) ? Wd[(size_t)(FDIM + r) * HDIM + colBase + cc]
                                 : b1[d * HDIM + colBase + cc];
        }
        float alpha = alphas[d];
        const float* W2d = W2 + (size_t)d * HDIM * KCOLS + (size_t)colBase * KCOLS;
#pragma unroll
        for (int i = 0; i < 8; i++) {
            int idx = i * 256 + tid;       // 0..2047
            int r = idx >> 4, cc = idx & 15;
            W2s[r * 17 + cc] = W2d[r * KCOLS + cc] * alpha;
        }
    }
    __syncthreads();

    // ---- epilogue: h = relu(acc + conf-tail + bias); dz-partial = h @ W2s ----
#pragma unroll
    for (int mf = 0; mf < 4; mf++) {
        int r0 = warp_m * 64 + mf * 16 + (lane >> 2);
        int na = sPerm[r0], nb = sPerm[r0 + 8];
        float a0 = 0.f, a1 = 0.f, a2 = 0.f, c0 = 0.f, c1 = 0.f, c2 = 0.f;
        if (na >= 0) { a0 = g_conf[na * 3]; a1 = g_conf[na * 3 + 1]; a2 = g_conf[na * 3 + 2]; }
        if (nb >= 0) { c0 = g_conf[nb * 3]; c1 = g_conf[nb * 3 + 1]; c2 = g_conf[nb * 3 + 2]; }
        float dzA[KCOLS], dzB[KCOLS];
#pragma unroll
        for (int c = 0; c < KCOLS; c++) { dzA[c] = 0.f; dzB[c] = 0.f; }
#pragma unroll
        for (int nf = 0; nf < 4; nf++) {
            int col = warp_n * 32 + nf * 8 + (lane & 3) * 2;
            float t0x = tails[col],       t0y = tails[col + 1];
            float t1x = tails[128 + col], t1y = tails[128 + col + 1];
            float t2x = tails[256 + col], t2y = tails[256 + col + 1];
            float tbx = tails[384 + col], tby = tails[384 + col + 1];
            float hxA = fmaxf(acc[mf][nf][0] + a0 * t0x + a1 * t1x + a2 * t2x + tbx, 0.f);
            float hyA = fmaxf(acc[mf][nf][1] + a0 * t0y + a1 * t1y + a2 * t2y + tby, 0.f);
            float hxB = fmaxf(acc[mf][nf][2] + c0 * t0x + c1 * t1x + c2 * t2x + tbx, 0.f);
            float hyB = fmaxf(acc[mf][nf][3] + c0 * t0y + c1 * t1y + c2 * t2y + tby, 0.f);
            const float* wx = W2s + col * 17;
            const float* wy = W2s + (col + 1) * 17;
#pragma unroll
            for (int c = 0; c < KCOLS; c++) {
                dzA[c] += hxA * wx[c] + hyA * wy[c];
                dzB[c] += hxB * wx[c] + hyB * wy[c];
            }
        }
        // quad reduce over lane&3 (lanes sharing a row)
#pragma unroll
        for (int off = 1; off <= 2; off <<= 1) {
#pragma unroll
            for (int c = 0; c < KCOLS; c++) {
                dzA[c] += __shfl_xor_sync(0xffffffffu, dzA[c], off);
                dzB[c] += __shfl_xor_sync(0xffffffffu, dzB[c], off);
            }
        }
        // stage this warp's 32-column partial in smem (per warp_n plane)
        int q = (lane & 3) * 4;
        *(float4*)(dzbuf + ((warp_n * 128 + r0) * KCOLS) + q) =
            make_float4(dzA[q], dzA[q + 1], dzA[q + 2], dzA[q + 3]);
        *(float4*)(dzbuf + ((warp_n * 128 + r0 + 8) * KCOLS) + q) =
            make_float4(dzB[q], dzB[q + 1], dzB[q + 2], dzB[q + 3]);
    }
    __syncthreads();

    // ---- deterministic cross-warp_n reduce: 512 float4 groups, 2 per thread ----
#pragma unroll
    for (int i = 0; i < 2; i++) {
        int idx = i * 256 + tid;          // 0..511  (float4 index)
        int row = idx >> 2, q = (idx & 3) * 4;
        int n = sPerm[row];
        if (n < 0) continue;
        float4 s0 = *(float4*)(dzbuf + ((0 * 128 + row) * KCOLS) + q);
        float4 s1 = *(float4*)(dzbuf + ((1 * 128 + row) * KCOLS) + q);
        float4 s2 = *(float4*)(dzbuf + ((2 * 128 + row) * KCOLS) + q);
        float4 s3 = *(float4*)(dzbuf + ((3 * 128 + row) * KCOLS) + q);
        float4 r;
        r.x = (s0.x + s1.x) + (s2.x + s3.x);
        r.y = (s0.y + s1.y) + (s2.y + s3.y);
        r.z = (s0.z + s1.z) + (s2.z + s3.z);
        r.w = (s0.w + s1.w) + (s2.w + s3.w);
        *(float4*)(g_dz + ((size_t)slice * NROWS + n) * KCOLS + q) = r;
    }
}

// ---------------- final: out = z, then out[:, cols[d]] += b2*alpha + sum dz ----------------
__global__ void k_final(const float* __restrict__ z, const int* __restrict__ dom,
                        const int* __restrict__ cols, const float* __restrict__ b2,
                        const float* __restrict__ alphas, float* __restrict__ out) {
    int row = blockIdx.x * 8 + (threadIdx.x >> 5);
    int lane = threadIdx.x & 31;
    ((float4*)out)[row * 32 + lane] = ((const float4*)z)[row * 32 + lane];
    __syncwarp();
    if (lane < KCOLS) {
        int d = dom[row];
        float s = b2[d * KCOLS + lane] * alphas[d];
#pragma unroll
        for (int sl = 0; sl < NSLICE; sl++)
            s += g_dz[((size_t)sl * NROWS + row) * KCOLS + lane];
        out[row * CDIM + cols[d * KCOLS + lane]] += s;
    }
}

// ---------------- launcher ----------------
extern "C" void kernel_launch(void* const* d_in, const int* in_sizes, int n_in,
                              void* d_out, int out_size) {
    const float* z      = (const float*)d_in[0];
    const int*   dom    = (const int*)d_in[1];
    const float* feats  = (const float*)d_in[2];
    const int*   cols   = (const int*)d_in[3];
    const float* W1     = (const float*)d_in[4];
    const float* b1     = (const float*)d_in[5];
    const float* W2     = (const float*)d_in[6];
    const float* b2     = (const float*)d_in[7];
    const float* alphas = (const float*)d_in[8];
    float* out = (float*)d_out;

    cudaFuncSetAttribute(k_gemm1, cudaFuncAttributeMaxDynamicSharedMemorySize, SMEM_SZ);

    k_zero<<<1, 32>>>();
    k_conf<<<NROWS / 256, 256>>>(z, dom, cols);
    k_scan<<<1, 1>>>();
    k_scatter<<<NROWS / 256, 256>>>(dom);
    k_cvtf<<<NROWS * FDIM / 4 / 256, 256>>>(feats);
    dim3 gw(FDIM / 32, HDIM / 32, NDOM);
    k_w1t<<<gw, dim3(32, 8)>>>(W1);

    dim3 g1(32, NSLICE, NDOM);   // over-provisioned row tiles; empty ones exit
    k_gemm1<<<g1, 256, SMEM_SZ>>>(W1, b1, W2, alphas, cols);

    k_final<<<NROWS / 8, 256>>>(z, dom, cols, b2, alphas, out);
}